// round 6
// baseline (speedup 1.0000x reference)
#include <cuda_runtime.h>
#include <math.h>
#include <stdint.h>

// ---------------- problem constants ----------------
#define D_MODEL 512
#define SEQ     1024
#define BATCH   8
#define NHEADS  8
#define UDIM    64
#define FF      2048
#define TOK     (BATCH*SEQ)          // 8192
#define LN_EPS  1e-3f

// ---------------- scratch (static device, allocation-guard safe) -------------
__device__ float g_Wq[D_MODEL*D_MODEL];
__device__ float g_Wk[D_MODEL*D_MODEL];
__device__ float g_Wv[D_MODEL*NHEADS*D_MODEL];
__device__ float g_Q [TOK*D_MODEL];
__device__ float g_Kb[TOK*D_MODEL];
__device__ float g_V [TOK*NHEADS*D_MODEL];
__device__ float g_S [(size_t)BATCH*NHEADS*SEQ*SEQ];
__device__ float g_A [TOK*NHEADS*D_MODEL];
__device__ float g_Mha[TOK*D_MODEL];
__device__ float g_H [TOK*D_MODEL];
__device__ float g_F1[TOK*FF];
__device__ float g_F2[TOK*D_MODEL];

// ---------------- cp.async helpers ----------------
__device__ __forceinline__ void cp_async4(unsigned int dst, const void* src) {
    asm volatile("cp.async.ca.shared.global [%0], [%1], 4;\n" :: "r"(dst), "l"(src));
}
__device__ __forceinline__ void cp_async16(unsigned int dst, const void* src) {
    asm volatile("cp.async.cg.shared.global [%0], [%1], 16;\n" :: "r"(dst), "l"(src));
}
__device__ __forceinline__ void cp_commit() {
    asm volatile("cp.async.commit_group;\n");
}
template<int N>
__device__ __forceinline__ void cp_wait() {
    asm volatile("cp.async.wait_group %0;\n" :: "n"(N));
}

// ---------------- weight pack: [H,D,U] -> [D, H*U] ----------------
__global__ void pack_w(const float* __restrict__ in, float* __restrict__ out,
                       int H, int D, int U) {
    int i = blockIdx.x * blockDim.x + threadIdx.x;
    int total = H * D * U;
    if (i >= total) return;
    int u = i % U;
    int d = (i / U) % D;
    int h = i / (U * D);
    out[d * (H * U) + h * U + u] = in[i];
}

// ---------------- tf32 tensor-core GEMM  128x128xK, 128 thr ----------------
// 4 warps, 2x2 grid, 64x64 warp tile.  mma.sync.m16n8k8.tf32, fp32 accum.
// smem: 3-stage cp.async pipeline, k-major tiles [16][128] with XOR swizzle:
//   element (k, m) stored at col (m ^ ((k&3)<<3))  -> all fragment LDS conflict-free.
// requires: M%128==0, N%128==0, K%16==0.
#define STAGES 3

template<bool TRANSB>
__global__ void __launch_bounds__(128) gemm_tc(
    const float* __restrict__ A, const float* __restrict__ B, float* __restrict__ C,
    int M, int N, int K, int lda, int ldb, int ldc,
    long long aOut, long long aIn, long long bOut, long long bIn,
    long long cOut, long long cIn, int HB,
    const float* __restrict__ bias, int relu)
{
    int z  = blockIdx.z;
    int zo = z / HB, zi = z % HB;
    A += zo * aOut + (long long)zi * aIn;
    B += zo * bOut + (long long)zi * bIn;
    C += zo * cOut + (long long)zi * cIn;

    __shared__ float As[STAGES][16][128];
    __shared__ float Bs[STAGES][16][128];

    const int tid  = threadIdx.x;
    const int lane = tid & 31;
    const int wid  = tid >> 5;
    const int wm   = wid >> 1;          // 0..1
    const int wn   = wid & 1;           // 0..1
    const int g    = lane >> 2;         // 0..7
    const int tig  = lane & 3;          // 0..3
    const int swz  = tig << 3;

    const int bm = blockIdx.y * 128;
    const int bn = blockIdx.x * 128;

    const int KT = K >> 4;              // # of 16-wide k tiles

    // ---- loader mappings ----
    // A: thread t owns gmem row (bm+t), 16 consecutive k floats -> scattered cp4
    const float* Agp = A + (long long)(bm + tid) * lda;
    // B non-trans: thread t owns (k-row t>>3, 16 cols at (t&7)*16) -> 4x cp16
    const int brow = tid >> 3;
    const int bcol = (tid & 7) * 16;
    // B trans: thread t owns gmem row (bn+t), 16 k floats -> scattered cp4
    const float* Bgp_t = B + (long long)(bn + tid) * ldb;

    unsigned int asBase = (unsigned int)__cvta_generic_to_shared(&As[0][0][0]);
    unsigned int bsBase = (unsigned int)__cvta_generic_to_shared(&Bs[0][0][0]);

    // issue async loads for tile kt into stage s
    auto issue = [&](int kt, int s) {
        unsigned int aS = asBase + (unsigned int)s * 16 * 128 * 4;
        const float* aSrc = Agp + kt * 16;
#pragma unroll
        for (int k = 0; k < 16; k++) {
            unsigned int dst = aS + (unsigned int)(k * 128 + (tid ^ ((k & 3) << 3))) * 4;
            cp_async4(dst, aSrc + k);
        }
        unsigned int bS = bsBase + (unsigned int)s * 16 * 128 * 4;
        if (TRANSB) {
            const float* bSrc = Bgp_t + kt * 16;
#pragma unroll
            for (int k = 0; k < 16; k++) {
                unsigned int dst = bS + (unsigned int)(k * 128 + (tid ^ ((k & 3) << 3))) * 4;
                cp_async4(dst, bSrc + k);
            }
        } else {
            const float* bSrc = B + (long long)(kt * 16 + brow) * ldb + bn + bcol;
#pragma unroll
            for (int i = 0; i < 4; i++) {
                // per-16B-group swizzle: (bcol+4i) ^ ((brow&3)<<3); 4i bits (2,3)
                // and swizzle bits (3,4) must be XORed together, not added.
                int col = (bcol + i * 4) ^ ((brow & 3) << 3);
                unsigned int dst = bS + (unsigned int)(brow * 128 + col) * 4;
                cp_async16(dst, bSrc + i * 4);
            }
        }
    };

    float acc[4][8][4];
#pragma unroll
    for (int mi = 0; mi < 4; mi++)
#pragma unroll
        for (int ni = 0; ni < 8; ni++)
#pragma unroll
            for (int r = 0; r < 4; r++) acc[mi][ni][r] = 0.f;

    // ---- prologue: fill STAGES-1 stages ----
#pragma unroll
    for (int s = 0; s < STAGES - 1; s++) {
        if (s < KT) issue(s, s);
        cp_commit();
    }

    for (int kt = 0; kt < KT; kt++) {
        cp_wait<STAGES - 2>();
        __syncthreads();

        // issue load for kt+STAGES-1 (overlaps with compute below)
        if (kt + STAGES - 1 < KT) issue(kt + STAGES - 1, (kt + STAGES - 1) % STAGES);
        cp_commit();

        const int st = kt % STAGES;
#pragma unroll
        for (int kk = 0; kk < 2; kk++) {
            const int kr = kk * 8 + tig;
            unsigned int af[4][4];
            unsigned int bf[8][2];
#pragma unroll
            for (int mi = 0; mi < 4; mi++) {
                const int m0 = wm * 64 + mi * 16 + g;
                af[mi][0] = __float_as_uint(As[st][kr    ][(m0    ) ^ swz]);
                af[mi][1] = __float_as_uint(As[st][kr    ][(m0 + 8) ^ swz]);
                af[mi][2] = __float_as_uint(As[st][kr + 4][(m0    ) ^ swz]);
                af[mi][3] = __float_as_uint(As[st][kr + 4][(m0 + 8) ^ swz]);
            }
#pragma unroll
            for (int ni = 0; ni < 8; ni++) {
                const int n0 = wn * 64 + ni * 8 + g;
                bf[ni][0] = __float_as_uint(Bs[st][kr    ][n0 ^ swz]);
                bf[ni][1] = __float_as_uint(Bs[st][kr + 4][n0 ^ swz]);
            }
#pragma unroll
            for (int mi = 0; mi < 4; mi++)
#pragma unroll
                for (int ni = 0; ni < 8; ni++) {
                    asm volatile(
                        "mma.sync.aligned.m16n8k8.row.col.f32.tf32.tf32.f32 "
                        "{%0,%1,%2,%3},{%4,%5,%6,%7},{%8,%9},{%0,%1,%2,%3};\n"
                        : "+f"(acc[mi][ni][0]), "+f"(acc[mi][ni][1]),
                          "+f"(acc[mi][ni][2]), "+f"(acc[mi][ni][3])
                        : "r"(af[mi][0]), "r"(af[mi][1]),
                          "r"(af[mi][2]), "r"(af[mi][3]),
                          "r"(bf[ni][0]), "r"(bf[ni][1]));
                }
        }
        __syncthreads();
    }

    // ---- epilogue ----
#pragma unroll
    for (int mi = 0; mi < 4; mi++) {
        const int row0 = bm + wm * 64 + mi * 16 + g;
#pragma unroll
        for (int ni = 0; ni < 8; ni++) {
            const int col = bn + wn * 64 + ni * 8 + tig * 2;
            float v0 = acc[mi][ni][0], v1 = acc[mi][ni][1];
            float v2 = acc[mi][ni][2], v3 = acc[mi][ni][3];
            if (bias) {
                float b0 = bias[col], b1 = bias[col + 1];
                v0 += b0; v1 += b1; v2 += b0; v3 += b1;
            }
            if (relu) {
                v0 = fmaxf(v0, 0.f); v1 = fmaxf(v1, 0.f);
                v2 = fmaxf(v2, 0.f); v3 = fmaxf(v3, 0.f);
            }
            *(float2*)(C + (long long)row0       * ldc + col) = make_float2(v0, v1);
            *(float2*)(C + (long long)(row0 + 8) * ldc + col) = make_float2(v2, v3);
        }
    }
}

// ---------------- row softmax over 1024 cols (with scale) ----------------
__global__ void softmax_1024(float* __restrict__ S, float scale) {
    long long row = blockIdx.x;
    float* p = S + row * 1024;
    int t = threadIdx.x;
    float4 v = *(float4*)(p + t * 4);
    v.x *= scale; v.y *= scale; v.z *= scale; v.w *= scale;

    __shared__ float red[256];
    float m = fmaxf(fmaxf(v.x, v.y), fmaxf(v.z, v.w));
    red[t] = m;
    __syncthreads();
#pragma unroll
    for (int s = 128; s > 0; s >>= 1) {
        if (t < s) red[t] = fmaxf(red[t], red[t + s]);
        __syncthreads();
    }
    m = red[0];
    __syncthreads();

    v.x = __expf(v.x - m); v.y = __expf(v.y - m);
    v.z = __expf(v.z - m); v.w = __expf(v.w - m);
    red[t] = v.x + v.y + v.z + v.w;
    __syncthreads();
#pragma unroll
    for (int s = 128; s > 0; s >>= 1) {
        if (t < s) red[t] += red[t + s];
        __syncthreads();
    }
    float inv = 1.f / red[0];
    v.x *= inv; v.y *= inv; v.z *= inv; v.w *= inv;
    *(float4*)(p + t * 4) = v;
}

// ---------------- out = LayerNorm(a + b) over 512 features ----------------
__global__ void add_ln(const float* __restrict__ a, const float* __restrict__ b,
                       const float* __restrict__ gamma, const float* __restrict__ beta,
                       float* __restrict__ out) {
    long long row = blockIdx.x;
    int t = threadIdx.x;
    const float4 va = ((const float4*)(a + row * 512))[t];
    const float4 vb = ((const float4*)(b + row * 512))[t];
    float x0 = va.x + vb.x, x1 = va.y + vb.y, x2 = va.z + vb.z, x3 = va.w + vb.w;

    __shared__ float red[128];
    red[t] = x0 + x1 + x2 + x3;
    __syncthreads();
#pragma unroll
    for (int s = 64; s > 0; s >>= 1) {
        if (t < s) red[t] += red[t + s];
        __syncthreads();
    }
    float mean = red[0] * (1.f / 512.f);
    __syncthreads();

    float d0 = x0 - mean, d1 = x1 - mean, d2 = x2 - mean, d3 = x3 - mean;
    red[t] = d0 * d0 + d1 * d1 + d2 * d2 + d3 * d3;
    __syncthreads();
#pragma unroll
    for (int s = 64; s > 0; s >>= 1) {
        if (t < s) red[t] += red[t + s];
        __syncthreads();
    }
    float var = red[0] * (1.f / 512.f);
    float inv = rsqrtf(var + LN_EPS);

    const float4 g = ((const float4*)gamma)[t];
    const float4 be = ((const float4*)beta)[t];
    float4 o;
    o.x = g.x * (d0 * inv) + be.x;
    o.y = g.y * (d1 * inv) + be.y;
    o.z = g.z * (d2 * inv) + be.z;
    o.w = g.w * (d3 * inv) + be.w;
    ((float4*)(out + row * 512))[t] = o;
}

// ---------------- launch ----------------
extern "C" void kernel_launch(void* const* d_in, const int* in_sizes, int n_in,
                              void* d_out, int out_size) {
    const float* x      = (const float*)d_in[0];
    const float* qw     = (const float*)d_in[1];
    const float* kw     = (const float*)d_in[2];
    const float* vw     = (const float*)d_in[3];
    const float* lw     = (const float*)d_in[4];
    const float* gamma1 = (const float*)d_in[5];
    const float* beta1  = (const float*)d_in[6];
    const float* w1     = (const float*)d_in[7];
    const float* b1     = (const float*)d_in[8];
    const float* w2     = (const float*)d_in[9];
    const float* b2     = (const float*)d_in[10];
    const float* gamma2 = (const float*)d_in[11];
    const float* beta2  = (const float*)d_in[12];
    float* out = (float*)d_out;

    float *Wq, *Wk, *Wv, *Q, *Kb, *V, *S, *A, *Mha, *H, *F1, *F2;
    cudaGetSymbolAddress((void**)&Wq,  g_Wq);
    cudaGetSymbolAddress((void**)&Wk,  g_Wk);
    cudaGetSymbolAddress((void**)&Wv,  g_Wv);
    cudaGetSymbolAddress((void**)&Q,   g_Q);
    cudaGetSymbolAddress((void**)&Kb,  g_Kb);
    cudaGetSymbolAddress((void**)&V,   g_V);
    cudaGetSymbolAddress((void**)&S,   g_S);
    cudaGetSymbolAddress((void**)&A,   g_A);
    cudaGetSymbolAddress((void**)&Mha, g_Mha);
    cudaGetSymbolAddress((void**)&H,   g_H);
    cudaGetSymbolAddress((void**)&F1,  g_F1);
    cudaGetSymbolAddress((void**)&F2,  g_F2);

    dim3 blk(128);

    pack_w<<<(8*512*64 + 255)/256, 256>>>(qw, Wq, 8, 512, 64);
    pack_w<<<(8*512*64 + 255)/256, 256>>>(kw, Wk, 8, 512, 64);
    pack_w<<<(8*512*512 + 255)/256, 256>>>(vw, Wv, 8, 512, 512);

    // Q = x @ Wq : [8192,512]
    gemm_tc<false><<<dim3(4, 64, 1), blk>>>(x, Wq, Q, 8192, 512, 512, 512, 512, 512,
                                            0, 0, 0, 0, 0, 0, 1, nullptr, 0);
    // K = x @ Wk
    gemm_tc<false><<<dim3(4, 64, 1), blk>>>(x, Wk, Kb, 8192, 512, 512, 512, 512, 512,
                                            0, 0, 0, 0, 0, 0, 1, nullptr, 0);
    // V = x @ Wv : [8192,4096]
    gemm_tc<false><<<dim3(32, 64, 1), blk>>>(x, Wv, V, 8192, 4096, 512, 512, 4096, 4096,
                                             0, 0, 0, 0, 0, 0, 1, nullptr, 0);

    // scores[z] = Q_bh @ K_bh^T : z=(b,h), NT, [1024,1024], K=64
    gemm_tc<true><<<dim3(8, 8, 64), blk>>>(Q, Kb, S, 1024, 1024, 64, 512, 512, 1024,
                                           1024LL*512, 64, 1024LL*512, 64,
                                           8LL*1024*1024, 1024LL*1024, 8, nullptr, 0);

    softmax_1024<<<64 * 1024, 256>>>(S, 1.0f / sqrtf(512.0f));

    // attn[z] = P @ V_bh -> concat-head layout [8192,4096]
    gemm_tc<false><<<dim3(4, 8, 64), blk>>>(S, V, A, 1024, 512, 1024, 1024, 4096, 4096,
                                            8LL*1024*1024, 1024LL*1024,
                                            1024LL*4096, 512,
                                            1024LL*4096, 512, 8, nullptr, 0);

    // mha = A @ lw : [8192,512]
    gemm_tc<false><<<dim3(4, 64, 1), blk>>>(A, lw, Mha, 8192, 512, 4096, 4096, 512, 512,
                                            0, 0, 0, 0, 0, 0, 1, nullptr, 0);

    add_ln<<<8192, 128>>>(x, Mha, gamma1, beta1, H);

    // F1 = relu(h @ w1 + b1) : [8192,2048]
    gemm_tc<false><<<dim3(16, 64, 1), blk>>>(H, w1, F1, 8192, 2048, 512, 512, 2048, 2048,
                                             0, 0, 0, 0, 0, 0, 1, b1, 1);

    // F2 = F1 @ w2 + b2 : [8192,512]
    gemm_tc<false><<<dim3(4, 64, 1), blk>>>(F1, w2, F2, 8192, 512, 2048, 2048, 512, 512,
                                            0, 0, 0, 0, 0, 0, 1, b2, 0);

    add_ln<<<8192, 128>>>(H, F2, gamma2, beta2, out);
}

// round 8
// speedup vs baseline: 1.9312x; 1.9312x over previous
#include <cuda_runtime.h>
#include <math.h>
#include <stdint.h>

// ---------------- problem constants ----------------
#define D_MODEL 512
#define SEQ     1024
#define BATCH   8
#define NHEADS  8
#define UDIM    64
#define FF      2048
#define TOK     (BATCH*SEQ)          // 8192
#define LN_EPS  1e-3f

// ---------------- scratch (static device, allocation-guard safe) -------------
__device__ float g_Wq[D_MODEL*D_MODEL];
__device__ float g_Wk[D_MODEL*D_MODEL];
__device__ float g_Wv[D_MODEL*NHEADS*D_MODEL];
__device__ float g_Q [TOK*D_MODEL];
__device__ float g_Kb[TOK*D_MODEL];
__device__ float g_V [TOK*NHEADS*D_MODEL];
__device__ float g_S [(size_t)BATCH*NHEADS*SEQ*SEQ];
__device__ float g_A [TOK*NHEADS*D_MODEL];
__device__ float g_Mha[TOK*D_MODEL];
__device__ float g_H [TOK*D_MODEL];
__device__ float g_F1[TOK*FF];
__device__ float g_F2[TOK*D_MODEL];

// ---------------- weight pack: [H,D,U] -> [D, H*U] ----------------
__global__ void pack_w(const float* __restrict__ in, float* __restrict__ out,
                       int H, int D, int U) {
    int i = blockIdx.x * blockDim.x + threadIdx.x;
    int total = H * D * U;
    if (i >= total) return;
    int u = i % U;
    int d = (i / U) % D;
    int h = i / (U * D);
    out[d * (H * U) + h * U + u] = in[i];
}

// ---------------- tf32 tensor-core GEMM  128x128xK, 256 thr ----------------
// 8 warps (2x4), 64x32 warp tile.  mma.sync.m16n8k8.tf32, fp32 accum.
// k-remap trick: fragment slot of thread t (=lane&3) carries global k {4t..4t+3}
// as one contiguous float4 (kk0:a0,a2 / kk1:a0,a2) = (x,y,z,w).  Both A and B
// use the same remap, so the k-sum is unchanged.  smem rows are plain k-major
// [row][16] with 16B-group swizzle  j -> j ^ ((row>>1)&3):
// every STS.128 and LDS.128 is bank-conflict-free (verified per 8-lane phase).
// 2-stage double buffer with register prefetch.
// requires: M%128==0, N%128==0, K%16==0.
template<bool TRANSB>
__global__ void __launch_bounds__(256) gemm_tc(
    const float* __restrict__ A, const float* __restrict__ B, float* __restrict__ C,
    int M, int N, int K, int lda, int ldb, int ldc,
    long long aOut, long long aIn, long long bOut, long long bIn,
    long long cOut, long long cIn, int HB,
    const float* __restrict__ bias, int relu)
{
    int z  = blockIdx.z;
    int zo = z / HB, zi = z % HB;
    A += zo * aOut + (long long)zi * aIn;
    B += zo * bOut + (long long)zi * bIn;
    C += zo * cOut + (long long)zi * cIn;

    __shared__ float4 As[2][128 * 4];   // [stage][row*4 + group16B]
    __shared__ float4 Bs[2][128 * 4];

    const int tid  = threadIdx.x;
    const int lane = tid & 31;
    const int wid  = tid >> 5;
    const int wm   = wid >> 2;          // 0..1  (64-row slab)
    const int wn   = wid & 3;           // 0..3  (32-col slab)
    const int g    = lane >> 2;         // 0..7
    const int t4   = lane & 3;          // 0..3

    const int bm = blockIdx.y * 128;
    const int bn = blockIdx.x * 128;
    const int KT = K >> 4;

    // ---- loader role: threads 0-127 load A rows, 128-255 load B rows ----
    const bool isA = (tid < 128);
    const int  lrow = isA ? tid : (tid - 128);
    const int  lsw  = (lrow >> 1) & 3;
    const float* Lg = isA ? (A + (long long)(bm + lrow) * lda)
                          : (TRANSB ? (B + (long long)(bn + lrow) * ldb) : B);

    float4 pf[4];
    auto ldtile = [&](int kt) {
        if (isA || TRANSB) {
            const float4* src = (const float4*)(Lg + kt * 16);
            pf[0] = src[0]; pf[1] = src[1]; pf[2] = src[2]; pf[3] = src[3];
        } else {
            const float* src = B + (long long)(kt * 16) * ldb + bn + lrow;
#pragma unroll
            for (int j = 0; j < 4; j++) {
                pf[j].x = src[(long long)(4 * j + 0) * ldb];
                pf[j].y = src[(long long)(4 * j + 1) * ldb];
                pf[j].z = src[(long long)(4 * j + 2) * ldb];
                pf[j].w = src[(long long)(4 * j + 3) * ldb];
            }
        }
    };
    auto sttile = [&](int s) {
        float4* dst = isA ? &As[s][0] : &Bs[s][0];
#pragma unroll
        for (int j = 0; j < 4; j++)
            dst[lrow * 4 + (j ^ lsw)] = pf[j];
    };

    float acc[4][4][4];
#pragma unroll
    for (int mi = 0; mi < 4; mi++)
#pragma unroll
        for (int ni = 0; ni < 4; ni++)
#pragma unroll
            for (int r = 0; r < 4; r++) acc[mi][ni][r] = 0.f;

    ldtile(0);
    sttile(0);
    __syncthreads();

    for (int kt = 0; kt < KT; kt++) {
        if (kt + 1 < KT) ldtile(kt + 1);   // LDG latency hidden by compute

        const int st = kt & 1;
        // ---- fragment loads: all LDS.128, conflict-free ----
        float4 afr[4][2];
#pragma unroll
        for (int mi = 0; mi < 4; mi++) {
            const int r0 = wm * 64 + mi * 16 + g;
            const int r1 = r0 + 8;
            afr[mi][0] = As[st][r0 * 4 + (t4 ^ ((r0 >> 1) & 3))];
            afr[mi][1] = As[st][r1 * 4 + (t4 ^ ((r1 >> 1) & 3))];
        }
#pragma unroll
        for (int ni = 0; ni < 4; ni++) {
            const int n0 = wn * 32 + ni * 8 + g;
            const float4 bfr = Bs[st][n0 * 4 + (t4 ^ ((n0 >> 1) & 3))];
#pragma unroll
            for (int mi = 0; mi < 4; mi++) {
                asm volatile(   // kk0: globals 4t,4t+1
                    "mma.sync.aligned.m16n8k8.row.col.f32.tf32.tf32.f32 "
                    "{%0,%1,%2,%3},{%4,%5,%6,%7},{%8,%9},{%0,%1,%2,%3};\n"
                    : "+f"(acc[mi][ni][0]), "+f"(acc[mi][ni][1]),
                      "+f"(acc[mi][ni][2]), "+f"(acc[mi][ni][3])
                    : "r"(__float_as_uint(afr[mi][0].x)), "r"(__float_as_uint(afr[mi][1].x)),
                      "r"(__float_as_uint(afr[mi][0].y)), "r"(__float_as_uint(afr[mi][1].y)),
                      "r"(__float_as_uint(bfr.x)), "r"(__float_as_uint(bfr.y)));
                asm volatile(   // kk1: globals 4t+2,4t+3
                    "mma.sync.aligned.m16n8k8.row.col.f32.tf32.tf32.f32 "
                    "{%0,%1,%2,%3},{%4,%5,%6,%7},{%8,%9},{%0,%1,%2,%3};\n"
                    : "+f"(acc[mi][ni][0]), "+f"(acc[mi][ni][1]),
                      "+f"(acc[mi][ni][2]), "+f"(acc[mi][ni][3])
                    : "r"(__float_as_uint(afr[mi][0].z)), "r"(__float_as_uint(afr[mi][1].z)),
                      "r"(__float_as_uint(afr[mi][0].w)), "r"(__float_as_uint(afr[mi][1].w)),
                      "r"(__float_as_uint(bfr.z)), "r"(__float_as_uint(bfr.w)));
            }
        }

        if (kt + 1 < KT) sttile((kt + 1) & 1);
        __syncthreads();
    }

    // ---- epilogue ----
#pragma unroll
    for (int mi = 0; mi < 4; mi++) {
        const int row0 = bm + wm * 64 + mi * 16 + g;
#pragma unroll
        for (int ni = 0; ni < 4; ni++) {
            const int col = bn + wn * 32 + ni * 8 + t4 * 2;
            float v0 = acc[mi][ni][0], v1 = acc[mi][ni][1];
            float v2 = acc[mi][ni][2], v3 = acc[mi][ni][3];
            if (bias) {
                float b0 = bias[col], b1 = bias[col + 1];
                v0 += b0; v1 += b1; v2 += b0; v3 += b1;
            }
            if (relu) {
                v0 = fmaxf(v0, 0.f); v1 = fmaxf(v1, 0.f);
                v2 = fmaxf(v2, 0.f); v3 = fmaxf(v3, 0.f);
            }
            *(float2*)(C + (long long)row0       * ldc + col) = make_float2(v0, v1);
            *(float2*)(C + (long long)(row0 + 8) * ldc + col) = make_float2(v2, v3);
        }
    }
}

// ---------------- row softmax over 1024 cols (with scale) ----------------
__global__ void softmax_1024(float* __restrict__ S, float scale) {
    long long row = blockIdx.x;
    float* p = S + row * 1024;
    int t = threadIdx.x;
    float4 v = *(float4*)(p + t * 4);
    v.x *= scale; v.y *= scale; v.z *= scale; v.w *= scale;

    __shared__ float red[256];
    float m = fmaxf(fmaxf(v.x, v.y), fmaxf(v.z, v.w));
    red[t] = m;
    __syncthreads();
#pragma unroll
    for (int s = 128; s > 0; s >>= 1) {
        if (t < s) red[t] = fmaxf(red[t], red[t + s]);
        __syncthreads();
    }
    m = red[0];
    __syncthreads();

    v.x = __expf(v.x - m); v.y = __expf(v.y - m);
    v.z = __expf(v.z - m); v.w = __expf(v.w - m);
    red[t] = v.x + v.y + v.z + v.w;
    __syncthreads();
#pragma unroll
    for (int s = 128; s > 0; s >>= 1) {
        if (t < s) red[t] += red[t + s];
        __syncthreads();
    }
    float inv = 1.f / red[0];
    v.x *= inv; v.y *= inv; v.z *= inv; v.w *= inv;
    *(float4*)(p + t * 4) = v;
}

// ---------------- out = LayerNorm(a + b) over 512 features ----------------
__global__ void add_ln(const float* __restrict__ a, const float* __restrict__ b,
                       const float* __restrict__ gamma, const float* __restrict__ beta,
                       float* __restrict__ out) {
    long long row = blockIdx.x;
    int t = threadIdx.x;
    const float4 va = ((const float4*)(a + row * 512))[t];
    const float4 vb = ((const float4*)(b + row * 512))[t];
    float x0 = va.x + vb.x, x1 = va.y + vb.y, x2 = va.z + vb.z, x3 = va.w + vb.w;

    __shared__ float red[128];
    red[t] = x0 + x1 + x2 + x3;
    __syncthreads();
#pragma unroll
    for (int s = 64; s > 0; s >>= 1) {
        if (t < s) red[t] += red[t + s];
        __syncthreads();
    }
    float mean = red[0] * (1.f / 512.f);
    __syncthreads();

    float d0 = x0 - mean, d1 = x1 - mean, d2 = x2 - mean, d3 = x3 - mean;
    red[t] = d0 * d0 + d1 * d1 + d2 * d2 + d3 * d3;
    __syncthreads();
#pragma unroll
    for (int s = 64; s > 0; s >>= 1) {
        if (t < s) red[t] += red[t + s];
        __syncthreads();
    }
    float var = red[0] * (1.f / 512.f);
    float inv = rsqrtf(var + LN_EPS);

    const float4 g = ((const float4*)gamma)[t];
    const float4 be = ((const float4*)beta)[t];
    float4 o;
    o.x = g.x * (d0 * inv) + be.x;
    o.y = g.y * (d1 * inv) + be.y;
    o.z = g.z * (d2 * inv) + be.z;
    o.w = g.w * (d3 * inv) + be.w;
    ((float4*)(out + row * 512))[t] = o;
}

// ---------------- launch ----------------
extern "C" void kernel_launch(void* const* d_in, const int* in_sizes, int n_in,
                              void* d_out, int out_size) {
    const float* x      = (const float*)d_in[0];
    const float* qw     = (const float*)d_in[1];
    const float* kw     = (const float*)d_in[2];
    const float* vw     = (const float*)d_in[3];
    const float* lw     = (const float*)d_in[4];
    const float* gamma1 = (const float*)d_in[5];
    const float* beta1  = (const float*)d_in[6];
    const float* w1     = (const float*)d_in[7];
    const float* b1     = (const float*)d_in[8];
    const float* w2     = (const float*)d_in[9];
    const float* b2     = (const float*)d_in[10];
    const float* gamma2 = (const float*)d_in[11];
    const float* beta2  = (const float*)d_in[12];
    float* out = (float*)d_out;

    float *Wq, *Wk, *Wv, *Q, *Kb, *V, *S, *A, *Mha, *H, *F1, *F2;
    cudaGetSymbolAddress((void**)&Wq,  g_Wq);
    cudaGetSymbolAddress((void**)&Wk,  g_Wk);
    cudaGetSymbolAddress((void**)&Wv,  g_Wv);
    cudaGetSymbolAddress((void**)&Q,   g_Q);
    cudaGetSymbolAddress((void**)&Kb,  g_Kb);
    cudaGetSymbolAddress((void**)&V,   g_V);
    cudaGetSymbolAddress((void**)&S,   g_S);
    cudaGetSymbolAddress((void**)&A,   g_A);
    cudaGetSymbolAddress((void**)&Mha, g_Mha);
    cudaGetSymbolAddress((void**)&H,   g_H);
    cudaGetSymbolAddress((void**)&F1,  g_F1);
    cudaGetSymbolAddress((void**)&F2,  g_F2);

    dim3 blk(256);

    pack_w<<<(8*512*64 + 255)/256, 256>>>(qw, Wq, 8, 512, 64);
    pack_w<<<(8*512*64 + 255)/256, 256>>>(kw, Wk, 8, 512, 64);
    pack_w<<<(8*512*512 + 255)/256, 256>>>(vw, Wv, 8, 512, 512);

    // Q = x @ Wq : [8192,512]
    gemm_tc<false><<<dim3(4, 64, 1), blk>>>(x, Wq, Q, 8192, 512, 512, 512, 512, 512,
                                            0, 0, 0, 0, 0, 0, 1, nullptr, 0);
    // K = x @ Wk
    gemm_tc<false><<<dim3(4, 64, 1), blk>>>(x, Wk, Kb, 8192, 512, 512, 512, 512, 512,
                                            0, 0, 0, 0, 0, 0, 1, nullptr, 0);
    // V = x @ Wv : [8192,4096]
    gemm_tc<false><<<dim3(32, 64, 1), blk>>>(x, Wv, V, 8192, 4096, 512, 512, 4096, 4096,
                                             0, 0, 0, 0, 0, 0, 1, nullptr, 0);

    // scores[z] = Q_bh @ K_bh^T : z=(b,h), NT, [1024,1024], K=64
    gemm_tc<true><<<dim3(8, 8, 64), blk>>>(Q, Kb, S, 1024, 1024, 64, 512, 512, 1024,
                                           1024LL*512, 64, 1024LL*512, 64,
                                           8LL*1024*1024, 1024LL*1024, 8, nullptr, 0);

    softmax_1024<<<64 * 1024, 256>>>(S, 1.0f / sqrtf(512.0f));

    // attn[z] = P @ V_bh -> concat-head layout [8192,4096]
    gemm_tc<false><<<dim3(4, 8, 64), blk>>>(S, V, A, 1024, 512, 1024, 1024, 4096, 4096,
                                            8LL*1024*1024, 1024LL*1024,
                                            1024LL*4096, 512,
                                            1024LL*4096, 512, 8, nullptr, 0);

    // mha = A @ lw : [8192,512]
    gemm_tc<false><<<dim3(4, 64, 1), blk>>>(A, lw, Mha, 8192, 512, 4096, 4096, 512, 512,
                                            0, 0, 0, 0, 0, 0, 1, nullptr, 0);

    add_ln<<<8192, 128>>>(x, Mha, gamma1, beta1, H);

    // F1 = relu(h @ w1 + b1) : [8192,2048]
    gemm_tc<false><<<dim3(16, 64, 1), blk>>>(H, w1, F1, 8192, 2048, 512, 512, 2048, 2048,
                                             0, 0, 0, 0, 0, 0, 1, b1, 1);

    // F2 = F1 @ w2 + b2 : [8192,512]
    gemm_tc<false><<<dim3(4, 64, 1), blk>>>(F1, w2, F2, 8192, 512, 2048, 2048, 512, 512,
                                            0, 0, 0, 0, 0, 0, 1, b2, 0);

    add_ln<<<8192, 128>>>(H, F2, gamma2, beta2, out);
}

// round 9
// speedup vs baseline: 2.1341x; 1.1051x over previous
#include <cuda_runtime.h>
#include <cuda_fp16.h>
#include <math.h>
#include <stdint.h>

// ---------------- problem constants ----------------
#define D_MODEL 512
#define SEQ     1024
#define BATCH   8
#define NHEADS  8
#define UDIM    64
#define FF      2048
#define TOK     (BATCH*SEQ)          // 8192
#define LN_EPS  1e-3f

// ---------------- scratch (static device, allocation-guard safe) -------------
__device__ float g_Wq[D_MODEL*D_MODEL];
__device__ float g_Wk[D_MODEL*D_MODEL];
__device__ float g_Wv[D_MODEL*NHEADS*D_MODEL];
__device__ float g_Q [TOK*D_MODEL];
__device__ float g_Kb[TOK*D_MODEL];
__device__ float g_V [TOK*NHEADS*D_MODEL];
__device__ float g_S [(size_t)BATCH*NHEADS*SEQ*SEQ];
__device__ float g_A [TOK*NHEADS*D_MODEL];
__device__ float g_Mha[TOK*D_MODEL];
__device__ float g_H [TOK*D_MODEL];
__device__ float g_F1[TOK*FF];
__device__ float g_F2[TOK*D_MODEL];

// ---------------- weight pack: [H,D,U] -> [D, H*U] ----------------
__global__ void pack_w(const float* __restrict__ in, float* __restrict__ out,
                       int H, int D, int U) {
    int i = blockIdx.x * blockDim.x + threadIdx.x;
    int total = H * D * U;
    if (i >= total) return;
    int u = i % U;
    int d = (i / U) % D;
    int h = i / (U * D);
    out[d * (H * U) + h * U + u] = in[i];
}

__device__ __forceinline__ unsigned h2pack(float a, float b) {
    __half2 h = __floats2half2_rn(a, b);
    return *reinterpret_cast<unsigned*>(&h);
}

// ---------------- fp16 tensor-core GEMM  128x128xK, 256 thr ----------------
// 8 warps (2x4), 64x32 warp tile.  mma.sync.m16n8k16.f16 (fp32 accum).
// Inputs converted fp32->fp16 in loader registers.
// smem: half rows [128][32] (64B/row), 16B-group swizzle j -> j ^ ((row>>1)&3):
//   STS.128 and all fragment LDS.64 bank-conflict-free (verified per phase).
// k-remap: thread t4 (lane&3) carries global k {4t4..4t4+3}; lo half2 -> a0/b0,
//   hi half2 -> a2/b1.  Same bijection for A and B -> k-sum unchanged.
// 2-stage double buffer with register prefetch.  K%32==0, M,N%128==0.
template<bool TRANSB>
__global__ void __launch_bounds__(256, 2) gemm_tc(
    const float* __restrict__ A, const float* __restrict__ B, float* __restrict__ C,
    int M, int N, int K, int lda, int ldb, int ldc,
    long long aOut, long long aIn, long long bOut, long long bIn,
    long long cOut, long long cIn, int HB,
    const float* __restrict__ bias, int relu)
{
    int z  = blockIdx.z;
    int zo = z / HB, zi = z % HB;
    A += zo * aOut + (long long)zi * aIn;
    B += zo * bOut + (long long)zi * bIn;
    C += zo * cOut + (long long)zi * cIn;

    __shared__ uint4 As[2][128 * 4];   // [stage][row*4 + 16Bgroup], 8 halves/group
    __shared__ uint4 Bs[2][128 * 4];

    const int tid  = threadIdx.x;
    const int lane = tid & 31;
    const int wid  = tid >> 5;
    const int wm   = wid >> 2;          // 0..1  (64-row slab)
    const int wn   = wid & 3;           // 0..3  (32-col slab)
    const int g    = lane >> 2;         // 0..7
    const int t4   = lane & 3;          // 0..3

    const int bm = blockIdx.y * 128;
    const int bn = blockIdx.x * 128;
    const int KT = K >> 5;              // k32 tiles

    // ---- loader role: threads 0-127 load A rows, 128-255 load B rows ----
    const bool isA = (tid < 128);
    const int  lrow = isA ? tid : (tid - 128);
    const int  lsw  = (lrow >> 1) & 3;
    const float* Lg = isA ? (A + (long long)(bm + lrow) * lda)
                          : (TRANSB ? (B + (long long)(bn + lrow) * ldb) : B);

    uint4 pf[4];   // 32 halves = one 64B row
    auto ldtile = [&](int kt) {
        if (isA || TRANSB) {
            const float4* src = (const float4*)(Lg + kt * 32);
#pragma unroll
            for (int j = 0; j < 4; j++) {
                float4 f0 = src[2 * j], f1 = src[2 * j + 1];
                pf[j] = make_uint4(h2pack(f0.x, f0.y), h2pack(f0.z, f0.w),
                                   h2pack(f1.x, f1.y), h2pack(f1.z, f1.w));
            }
        } else {
            const float* src = B + (long long)(kt * 32) * ldb + bn + lrow;
#pragma unroll
            for (int j = 0; j < 4; j++) {
                float v[8];
#pragma unroll
                for (int i = 0; i < 8; i++)
                    v[i] = src[(long long)(8 * j + i) * ldb];
                pf[j] = make_uint4(h2pack(v[0], v[1]), h2pack(v[2], v[3]),
                                   h2pack(v[4], v[5]), h2pack(v[6], v[7]));
            }
        }
    };
    auto sttile = [&](int s) {
        uint4* dst = isA ? &As[s][0] : &Bs[s][0];
#pragma unroll
        for (int j = 0; j < 4; j++)
            dst[lrow * 4 + (j ^ lsw)] = pf[j];
    };

    float acc[4][4][4];
#pragma unroll
    for (int mi = 0; mi < 4; mi++)
#pragma unroll
        for (int ni = 0; ni < 4; ni++)
#pragma unroll
            for (int r = 0; r < 4; r++) acc[mi][ni][r] = 0.f;

    ldtile(0);
    sttile(0);
    __syncthreads();

    for (int kt = 0; kt < KT; kt++) {
        if (kt + 1 < KT) ldtile(kt + 1);   // LDG hidden under MMAs

        const uint2* As2 = (const uint2*)&As[kt & 1][0];
        const uint2* Bs2 = (const uint2*)&Bs[kt & 1][0];
        // uint2 index of (row r, sub-tile kk): r*8 + ((kk*2+(t4>>1)) ^ ((r>>1)&3))*2 + (t4&1)
#pragma unroll
        for (int kk = 0; kk < 2; kk++) {
            uint2 afr[4][2];
#pragma unroll
            for (int mi = 0; mi < 4; mi++) {
                const int r0 = wm * 64 + mi * 16 + g;
                const int r1 = r0 + 8;
                const int jb = kk * 2 + (t4 >> 1);
                afr[mi][0] = As2[r0 * 8 + ((jb ^ ((r0 >> 1) & 3)) << 1) + (t4 & 1)];
                afr[mi][1] = As2[r1 * 8 + ((jb ^ ((r1 >> 1) & 3)) << 1) + (t4 & 1)];
            }
#pragma unroll
            for (int ni = 0; ni < 4; ni++) {
                const int n0 = wn * 32 + ni * 8 + g;
                const int jb = kk * 2 + (t4 >> 1);
                const uint2 bfr = Bs2[n0 * 8 + ((jb ^ ((n0 >> 1) & 3)) << 1) + (t4 & 1)];
#pragma unroll
                for (int mi = 0; mi < 4; mi++) {
                    asm volatile(
                        "mma.sync.aligned.m16n8k16.row.col.f32.f16.f16.f32 "
                        "{%0,%1,%2,%3},{%4,%5,%6,%7},{%8,%9},{%0,%1,%2,%3};\n"
                        : "+f"(acc[mi][ni][0]), "+f"(acc[mi][ni][1]),
                          "+f"(acc[mi][ni][2]), "+f"(acc[mi][ni][3])
                        : "r"(afr[mi][0].x), "r"(afr[mi][1].x),
                          "r"(afr[mi][0].y), "r"(afr[mi][1].y),
                          "r"(bfr.x), "r"(bfr.y));
                }
            }
        }

        if (kt + 1 < KT) sttile((kt + 1) & 1);
        __syncthreads();
    }

    // ---- epilogue ----
#pragma unroll
    for (int mi = 0; mi < 4; mi++) {
        const int row0 = bm + wm * 64 + mi * 16 + g;
#pragma unroll
        for (int ni = 0; ni < 4; ni++) {
            const int col = bn + wn * 32 + ni * 8 + t4 * 2;
            float v0 = acc[mi][ni][0], v1 = acc[mi][ni][1];
            float v2 = acc[mi][ni][2], v3 = acc[mi][ni][3];
            if (bias) {
                float b0 = bias[col], b1 = bias[col + 1];
                v0 += b0; v1 += b1; v2 += b0; v3 += b1;
            }
            if (relu) {
                v0 = fmaxf(v0, 0.f); v1 = fmaxf(v1, 0.f);
                v2 = fmaxf(v2, 0.f); v3 = fmaxf(v3, 0.f);
            }
            *(float2*)(C + (long long)row0       * ldc + col) = make_float2(v0, v1);
            *(float2*)(C + (long long)(row0 + 8) * ldc + col) = make_float2(v2, v3);
        }
    }
}

// ---------------- row softmax over 1024 cols (with scale) ----------------
__global__ void softmax_1024(float* __restrict__ S, float scale) {
    long long row = blockIdx.x;
    float* p = S + row * 1024;
    int t = threadIdx.x;
    float4 v = *(float4*)(p + t * 4);
    v.x *= scale; v.y *= scale; v.z *= scale; v.w *= scale;

    __shared__ float red[256];
    float m = fmaxf(fmaxf(v.x, v.y), fmaxf(v.z, v.w));
    red[t] = m;
    __syncthreads();
#pragma unroll
    for (int s = 128; s > 0; s >>= 1) {
        if (t < s) red[t] = fmaxf(red[t], red[t + s]);
        __syncthreads();
    }
    m = red[0];
    __syncthreads();

    v.x = __expf(v.x - m); v.y = __expf(v.y - m);
    v.z = __expf(v.z - m); v.w = __expf(v.w - m);
    red[t] = v.x + v.y + v.z + v.w;
    __syncthreads();
#pragma unroll
    for (int s = 128; s > 0; s >>= 1) {
        if (t < s) red[t] += red[t + s];
        __syncthreads();
    }
    float inv = 1.f / red[0];
    v.x *= inv; v.y *= inv; v.z *= inv; v.w *= inv;
    *(float4*)(p + t * 4) = v;
}

// ---------------- out = LayerNorm(a + b) over 512 features ----------------
__global__ void add_ln(const float* __restrict__ a, const float* __restrict__ b,
                       const float* __restrict__ gamma, const float* __restrict__ beta,
                       float* __restrict__ out) {
    long long row = blockIdx.x;
    int t = threadIdx.x;
    const float4 va = ((const float4*)(a + row * 512))[t];
    const float4 vb = ((const float4*)(b + row * 512))[t];
    float x0 = va.x + vb.x, x1 = va.y + vb.y, x2 = va.z + vb.z, x3 = va.w + vb.w;

    __shared__ float red[128];
    red[t] = x0 + x1 + x2 + x3;
    __syncthreads();
#pragma unroll
    for (int s = 64; s > 0; s >>= 1) {
        if (t < s) red[t] += red[t + s];
        __syncthreads();
    }
    float mean = red[0] * (1.f / 512.f);
    __syncthreads();

    float d0 = x0 - mean, d1 = x1 - mean, d2 = x2 - mean, d3 = x3 - mean;
    red[t] = d0 * d0 + d1 * d1 + d2 * d2 + d3 * d3;
    __syncthreads();
#pragma unroll
    for (int s = 64; s > 0; s >>= 1) {
        if (t < s) red[t] += red[t + s];
        __syncthreads();
    }
    float var = red[0] * (1.f / 512.f);
    float inv = rsqrtf(var + LN_EPS);

    const float4 g = ((const float4*)gamma)[t];
    const float4 be = ((const float4*)beta)[t];
    float4 o;
    o.x = g.x * (d0 * inv) + be.x;
    o.y = g.y * (d1 * inv) + be.y;
    o.z = g.z * (d2 * inv) + be.z;
    o.w = g.w * (d3 * inv) + be.w;
    ((float4*)(out + row * 512))[t] = o;
}

// ---------------- launch ----------------
extern "C" void kernel_launch(void* const* d_in, const int* in_sizes, int n_in,
                              void* d_out, int out_size) {
    const float* x      = (const float*)d_in[0];
    const float* qw     = (const float*)d_in[1];
    const float* kw     = (const float*)d_in[2];
    const float* vw     = (const float*)d_in[3];
    const float* lw     = (const float*)d_in[4];
    const float* gamma1 = (const float*)d_in[5];
    const float* beta1  = (const float*)d_in[6];
    const float* w1     = (const float*)d_in[7];
    const float* b1     = (const float*)d_in[8];
    const float* w2     = (const float*)d_in[9];
    const float* b2     = (const float*)d_in[10];
    const float* gamma2 = (const float*)d_in[11];
    const float* beta2  = (const float*)d_in[12];
    float* out = (float*)d_out;

    float *Wq, *Wk, *Wv, *Q, *Kb, *V, *S, *A, *Mha, *H, *F1, *F2;
    cudaGetSymbolAddress((void**)&Wq,  g_Wq);
    cudaGetSymbolAddress((void**)&Wk,  g_Wk);
    cudaGetSymbolAddress((void**)&Wv,  g_Wv);
    cudaGetSymbolAddress((void**)&Q,   g_Q);
    cudaGetSymbolAddress((void**)&Kb,  g_Kb);
    cudaGetSymbolAddress((void**)&V,   g_V);
    cudaGetSymbolAddress((void**)&S,   g_S);
    cudaGetSymbolAddress((void**)&A,   g_A);
    cudaGetSymbolAddress((void**)&Mha, g_Mha);
    cudaGetSymbolAddress((void**)&H,   g_H);
    cudaGetSymbolAddress((void**)&F1,  g_F1);
    cudaGetSymbolAddress((void**)&F2,  g_F2);

    dim3 blk(256);

    pack_w<<<(8*512*64 + 255)/256, 256>>>(qw, Wq, 8, 512, 64);
    pack_w<<<(8*512*64 + 255)/256, 256>>>(kw, Wk, 8, 512, 64);
    pack_w<<<(8*512*512 + 255)/256, 256>>>(vw, Wv, 8, 512, 512);

    // Q = x @ Wq : [8192,512]
    gemm_tc<false><<<dim3(4, 64, 1), blk>>>(x, Wq, Q, 8192, 512, 512, 512, 512, 512,
                                            0, 0, 0, 0, 0, 0, 1, nullptr, 0);
    // K = x @ Wk
    gemm_tc<false><<<dim3(4, 64, 1), blk>>>(x, Wk, Kb, 8192, 512, 512, 512, 512, 512,
                                            0, 0, 0, 0, 0, 0, 1, nullptr, 0);
    // V = x @ Wv : [8192,4096]
    gemm_tc<false><<<dim3(32, 64, 1), blk>>>(x, Wv, V, 8192, 4096, 512, 512, 4096, 4096,
                                             0, 0, 0, 0, 0, 0, 1, nullptr, 0);

    // scores[z] = Q_bh @ K_bh^T : z=(b,h), NT, [1024,1024], K=64
    gemm_tc<true><<<dim3(8, 8, 64), blk>>>(Q, Kb, S, 1024, 1024, 64, 512, 512, 1024,
                                           1024LL*512, 64, 1024LL*512, 64,
                                           8LL*1024*1024, 1024LL*1024, 8, nullptr, 0);

    softmax_1024<<<64 * 1024, 256>>>(S, 1.0f / sqrtf(512.0f));

    // attn[z] = P @ V_bh -> concat-head layout [8192,4096]
    gemm_tc<false><<<dim3(4, 8, 64), blk>>>(S, V, A, 1024, 512, 1024, 1024, 4096, 4096,
                                            8LL*1024*1024, 1024LL*1024,
                                            1024LL*4096, 512,
                                            1024LL*4096, 512, 8, nullptr, 0);

    // mha = A @ lw : [8192,512]
    gemm_tc<false><<<dim3(4, 64, 1), blk>>>(A, lw, Mha, 8192, 512, 4096, 4096, 512, 512,
                                            0, 0, 0, 0, 0, 0, 1, nullptr, 0);

    add_ln<<<8192, 128>>>(x, Mha, gamma1, beta1, H);

    // F1 = relu(h @ w1 + b1) : [8192,2048]
    gemm_tc<false><<<dim3(16, 64, 1), blk>>>(H, w1, F1, 8192, 2048, 512, 512, 2048, 2048,
                                             0, 0, 0, 0, 0, 0, 1, b1, 1);

    // F2 = F1 @ w2 + b2 : [8192,512]
    gemm_tc<false><<<dim3(4, 64, 1), blk>>>(F1, w2, F2, 8192, 512, 2048, 2048, 512, 512,
                                            0, 0, 0, 0, 0, 0, 1, b2, 0);

    add_ln<<<8192, 128>>>(H, F2, gamma2, beta2, out);
}

// round 10
// speedup vs baseline: 2.7904x; 1.3075x over previous
#include <cuda_runtime.h>
#include <cuda_fp16.h>
#include <math.h>
#include <stdint.h>

// ---------------- problem constants ----------------
#define D_MODEL 512
#define SEQ     1024
#define BATCH   8
#define NHEADS  8
#define UDIM    64
#define FF      2048
#define TOK     (BATCH*SEQ)          // 8192
#define LN_EPS  1e-3f

// ---------------- scratch (static device, allocation-guard safe) -------------
__device__ __half g_x16[TOK*D_MODEL];
__device__ __half g_WqT[D_MODEL*D_MODEL];            // [n=h*64+u][k=d]
__device__ __half g_WkT[D_MODEL*D_MODEL];
__device__ __half g_WvT[NHEADS*D_MODEL*D_MODEL];     // [n=h*512+e][k=d]
__device__ __half g_lwT[D_MODEL*NHEADS*D_MODEL];     // [n=512][k=4096]
__device__ __half g_w1T[FF*D_MODEL];                 // [2048][512]
__device__ __half g_w2T[D_MODEL*FF];                 // [512][2048]
__device__ __half g_Q16[TOK*D_MODEL];
__device__ __half g_K16[TOK*D_MODEL];
__device__ __half g_V16[TOK*NHEADS*D_MODEL];         // [token][h*512+e]
__device__ __half g_Vt [(size_t)BATCH*NHEADS*D_MODEL*SEQ];  // [z][e][t]
__device__ float  g_S  [(size_t)BATCH*NHEADS*SEQ*SEQ];      // fp32 scores
__device__ __half g_S16[(size_t)BATCH*NHEADS*SEQ*SEQ];      // fp16 probs
__device__ __half g_A16[TOK*NHEADS*D_MODEL];
__device__ float  g_Mha[TOK*D_MODEL];
__device__ float  g_H  [TOK*D_MODEL];
__device__ __half g_H16[TOK*D_MODEL];
__device__ __half g_F1 [TOK*FF];
__device__ float  g_F2 [TOK*D_MODEL];

// ---------------- cp.async helpers ----------------
__device__ __forceinline__ void cp_async16(unsigned int dst, const void* src) {
    asm volatile("cp.async.cg.shared.global [%0], [%1], 16;\n" :: "r"(dst), "l"(src));
}
__device__ __forceinline__ void cp_commit() {
    asm volatile("cp.async.commit_group;\n");
}
template<int N>
__device__ __forceinline__ void cp_wait() {
    asm volatile("cp.async.wait_group %0;\n" :: "n"(N));
}

// ---------------- elementwise fp32 -> fp16 ----------------
__global__ void cvt16(const float* __restrict__ in, __half* __restrict__ out, int n) {
    int i = blockIdx.x * blockDim.x + threadIdx.x;
    if (i < n) out[i] = __float2half(in[i]);
}

// ---------------- tiled transpose + cvt: in[z][R][C] fp32 -> out[z][C][R] fp16 --
// R, C multiples of 32.  32x32 tiles, 32x8 threads.
__global__ void transpose_cvt(const float* __restrict__ in, __half* __restrict__ out,
                              int R, int C, long long inZ, long long outZ) {
    in  += (long long)blockIdx.z * inZ;
    out += (long long)blockIdx.z * outZ;
    __shared__ float s[32][33];
    int c0 = blockIdx.x * 32, r0 = blockIdx.y * 32;
    int tx = threadIdx.x, ty = threadIdx.y;
#pragma unroll
    for (int j = 0; j < 4; j++)
        s[ty + 8 * j][tx] = in[(long long)(r0 + ty + 8 * j) * C + c0 + tx];
    __syncthreads();
#pragma unroll
    for (int j = 0; j < 4; j++)
        out[(long long)(c0 + ty + 8 * j) * R + r0 + tx] = __float2half(s[tx][ty + 8 * j]);
}

// ---------------- V transpose: V16[token][h*512+e] -> Vt[z][e][t] ----------------
__global__ void transpose_v(const __half* __restrict__ V16, __half* __restrict__ Vt) {
    int z = blockIdx.z, b = z >> 3, h = z & 7;
    int c0 = blockIdx.x * 32;   // e
    int r0 = blockIdx.y * 32;   // t
    __shared__ __half s[32][40];
    int tx = threadIdx.x, ty = threadIdx.y;
#pragma unroll
    for (int j = 0; j < 4; j++)
        s[ty + 8 * j][tx] = V16[(size_t)(b * 1024 + r0 + ty + 8 * j) * 4096 + h * 512 + c0 + tx];
    __syncthreads();
#pragma unroll
    for (int j = 0; j < 4; j++)
        Vt[(size_t)z * 512 * 1024 + (size_t)(c0 + ty + 8 * j) * 1024 + r0 + tx] = s[tx][ty + 8 * j];
}

// ---------------- fp16 NT tensor-core GEMM  128x128xK, 256 thr ----------------
// Both operands k-major fp16 rows.  8 warps (2x4), 64x32 warp tile,
// mma.sync.m16n8k16 (fp32 accum).  smem rows 32 halves (64B), 16B-group
// swizzle j -> j ^ ((row>>1)&3): STS/LDS conflict-free (verified).
// k-remap: thread t4 carries global k {4t4..4t4+3}; same bijection A and B.
// 3-stage cp.async pipeline (4x cp16 per thread per k32-tile).
// C written fp32 (C32) and/or fp16 (C16).  K%32==0, M,N%128==0.
#define STAGES 3
__global__ void __launch_bounds__(256, 2) gemm16(
    const __half* __restrict__ A, const __half* __restrict__ B,
    float* __restrict__ C32, __half* __restrict__ C16,
    int M, int N, int K, int lda, int ldb, int ldc,
    long long aOut, long long aIn, long long bOut, long long bIn,
    long long cOut, long long cIn, int HB,
    const float* __restrict__ bias, int relu)
{
    int z  = blockIdx.z;
    int zo = z / HB, zi = z % HB;
    A += zo * aOut + (long long)zi * aIn;
    B += zo * bOut + (long long)zi * bIn;
    long long coff = zo * cOut + (long long)zi * cIn;

    __shared__ uint4 As[STAGES][128 * 4];
    __shared__ uint4 Bs[STAGES][128 * 4];

    const int tid  = threadIdx.x;
    const int lane = tid & 31;
    const int wid  = tid >> 5;
    const int wm   = wid >> 2;
    const int wn   = wid & 3;
    const int g    = lane >> 2;
    const int t4   = lane & 3;

    const int bm = blockIdx.y * 128;
    const int bn = blockIdx.x * 128;
    const int KT = K >> 5;

    const bool isA = (tid < 128);
    const int  lrow = isA ? tid : (tid - 128);
    const int  lsw  = (lrow >> 1) & 3;
    const __half* Lg = isA ? (A + (long long)(bm + lrow) * lda)
                           : (B + (long long)(bn + lrow) * ldb);

    unsigned int sBase = (unsigned int)__cvta_generic_to_shared(
        isA ? &As[0][0] : &Bs[0][0]);

    auto issue = [&](int kt, int s) {
        unsigned int st = sBase + (unsigned int)s * 128 * 4 * 16;
        const __half* src = Lg + kt * 32;
#pragma unroll
        for (int j = 0; j < 4; j++)
            cp_async16(st + (unsigned int)(lrow * 4 + (j ^ lsw)) * 16, src + j * 8);
    };

    float acc[4][4][4];
#pragma unroll
    for (int mi = 0; mi < 4; mi++)
#pragma unroll
        for (int ni = 0; ni < 4; ni++)
#pragma unroll
            for (int r = 0; r < 4; r++) acc[mi][ni][r] = 0.f;

#pragma unroll
    for (int s = 0; s < STAGES - 1; s++) {
        if (s < KT) issue(s, s);
        cp_commit();
    }

    for (int kt = 0; kt < KT; kt++) {
        cp_wait<STAGES - 2>();
        __syncthreads();
        if (kt + STAGES - 1 < KT) issue(kt + STAGES - 1, (kt + STAGES - 1) % STAGES);
        cp_commit();

        const uint2* As2 = (const uint2*)&As[kt % STAGES][0];
        const uint2* Bs2 = (const uint2*)&Bs[kt % STAGES][0];
#pragma unroll
        for (int kk = 0; kk < 2; kk++) {
            const int jb = kk * 2 + (t4 >> 1);
            uint2 afr[4][2];
#pragma unroll
            for (int mi = 0; mi < 4; mi++) {
                const int r0 = wm * 64 + mi * 16 + g;
                const int r1 = r0 + 8;
                afr[mi][0] = As2[r0 * 8 + ((jb ^ ((r0 >> 1) & 3)) << 1) + (t4 & 1)];
                afr[mi][1] = As2[r1 * 8 + ((jb ^ ((r1 >> 1) & 3)) << 1) + (t4 & 1)];
            }
#pragma unroll
            for (int ni = 0; ni < 4; ni++) {
                const int n0 = wn * 32 + ni * 8 + g;
                const uint2 bfr = Bs2[n0 * 8 + ((jb ^ ((n0 >> 1) & 3)) << 1) + (t4 & 1)];
#pragma unroll
                for (int mi = 0; mi < 4; mi++) {
                    asm volatile(
                        "mma.sync.aligned.m16n8k16.row.col.f32.f16.f16.f32 "
                        "{%0,%1,%2,%3},{%4,%5,%6,%7},{%8,%9},{%0,%1,%2,%3};\n"
                        : "+f"(acc[mi][ni][0]), "+f"(acc[mi][ni][1]),
                          "+f"(acc[mi][ni][2]), "+f"(acc[mi][ni][3])
                        : "r"(afr[mi][0].x), "r"(afr[mi][1].x),
                          "r"(afr[mi][0].y), "r"(afr[mi][1].y),
                          "r"(bfr.x), "r"(bfr.y));
                }
            }
        }
        __syncthreads();
    }

    // ---- epilogue ----
#pragma unroll
    for (int mi = 0; mi < 4; mi++) {
        const int row0 = bm + wm * 64 + mi * 16 + g;
#pragma unroll
        for (int ni = 0; ni < 4; ni++) {
            const int col = bn + wn * 32 + ni * 8 + t4 * 2;
            float v0 = acc[mi][ni][0], v1 = acc[mi][ni][1];
            float v2 = acc[mi][ni][2], v3 = acc[mi][ni][3];
            if (bias) {
                float b0 = bias[col], b1 = bias[col + 1];
                v0 += b0; v1 += b1; v2 += b0; v3 += b1;
            }
            if (relu) {
                v0 = fmaxf(v0, 0.f); v1 = fmaxf(v1, 0.f);
                v2 = fmaxf(v2, 0.f); v3 = fmaxf(v3, 0.f);
            }
            long long o0 = coff + (long long)row0 * ldc + col;
            long long o1 = coff + (long long)(row0 + 8) * ldc + col;
            if (C32) {
                *(float2*)(C32 + o0) = make_float2(v0, v1);
                *(float2*)(C32 + o1) = make_float2(v2, v3);
            }
            if (C16) {
                *(__half2*)(C16 + o0) = __floats2half2_rn(v0, v1);
                *(__half2*)(C16 + o1) = __floats2half2_rn(v2, v3);
            }
        }
    }
}

// ---------------- row softmax over 1024 cols: fp32 in -> fp16 out ------------
__global__ void softmax_1024(const float* __restrict__ S, __half* __restrict__ P,
                             float scale) {
    long long row = blockIdx.x;
    const float* p = S + row * 1024;
    int t = threadIdx.x;
    float4 v = ((const float4*)p)[t];
    v.x *= scale; v.y *= scale; v.z *= scale; v.w *= scale;

    __shared__ float red[256];
    float m = fmaxf(fmaxf(v.x, v.y), fmaxf(v.z, v.w));
    red[t] = m;
    __syncthreads();
#pragma unroll
    for (int s = 128; s > 0; s >>= 1) {
        if (t < s) red[t] = fmaxf(red[t], red[t + s]);
        __syncthreads();
    }
    m = red[0];
    __syncthreads();

    v.x = __expf(v.x - m); v.y = __expf(v.y - m);
    v.z = __expf(v.z - m); v.w = __expf(v.w - m);
    red[t] = v.x + v.y + v.z + v.w;
    __syncthreads();
#pragma unroll
    for (int s = 128; s > 0; s >>= 1) {
        if (t < s) red[t] += red[t + s];
        __syncthreads();
    }
    float inv = 1.f / red[0];
    __half2* o = (__half2*)(P + row * 1024);
    o[2 * t]     = __floats2half2_rn(v.x * inv, v.y * inv);
    o[2 * t + 1] = __floats2half2_rn(v.z * inv, v.w * inv);
}

// ---------------- out = LayerNorm(a + b); optional fp16 copy ----------------
__global__ void add_ln(const float* __restrict__ a, const float* __restrict__ b,
                       const float* __restrict__ gamma, const float* __restrict__ beta,
                       float* __restrict__ out, __half* __restrict__ out16) {
    long long row = blockIdx.x;
    int t = threadIdx.x;
    const float4 va = ((const float4*)(a + row * 512))[t];
    const float4 vb = ((const float4*)(b + row * 512))[t];
    float x0 = va.x + vb.x, x1 = va.y + vb.y, x2 = va.z + vb.z, x3 = va.w + vb.w;

    __shared__ float red[128];
    red[t] = x0 + x1 + x2 + x3;
    __syncthreads();
#pragma unroll
    for (int s = 64; s > 0; s >>= 1) {
        if (t < s) red[t] += red[t + s];
        __syncthreads();
    }
    float mean = red[0] * (1.f / 512.f);
    __syncthreads();

    float d0 = x0 - mean, d1 = x1 - mean, d2 = x2 - mean, d3 = x3 - mean;
    red[t] = d0 * d0 + d1 * d1 + d2 * d2 + d3 * d3;
    __syncthreads();
#pragma unroll
    for (int s = 64; s > 0; s >>= 1) {
        if (t < s) red[t] += red[t + s];
        __syncthreads();
    }
    float var = red[0] * (1.f / 512.f);
    float inv = rsqrtf(var + LN_EPS);

    const float4 gm = ((const float4*)gamma)[t];
    const float4 be = ((const float4*)beta)[t];
    float4 o;
    o.x = gm.x * (d0 * inv) + be.x;
    o.y = gm.y * (d1 * inv) + be.y;
    o.z = gm.z * (d2 * inv) + be.z;
    o.w = gm.w * (d3 * inv) + be.w;
    ((float4*)(out + row * 512))[t] = o;
    if (out16) {
        __half2* h = (__half2*)(out16 + row * 512);
        h[2 * t]     = __floats2half2_rn(o.x, o.y);
        h[2 * t + 1] = __floats2half2_rn(o.z, o.w);
    }
}

// ---------------- launch ----------------
extern "C" void kernel_launch(void* const* d_in, const int* in_sizes, int n_in,
                              void* d_out, int out_size) {
    const float* x      = (const float*)d_in[0];
    const float* qw     = (const float*)d_in[1];
    const float* kw     = (const float*)d_in[2];
    const float* vw     = (const float*)d_in[3];
    const float* lw     = (const float*)d_in[4];
    const float* gamma1 = (const float*)d_in[5];
    const float* beta1  = (const float*)d_in[6];
    const float* w1     = (const float*)d_in[7];
    const float* b1     = (const float*)d_in[8];
    const float* w2     = (const float*)d_in[9];
    const float* b2     = (const float*)d_in[10];
    const float* gamma2 = (const float*)d_in[11];
    const float* beta2  = (const float*)d_in[12];
    float* out = (float*)d_out;

    __half *x16, *WqT, *WkT, *WvT, *lwT, *w1T, *w2T, *Q16, *K16, *V16, *Vt,
           *S16, *A16, *H16, *F1;
    float *S, *Mha, *H, *F2;
    cudaGetSymbolAddress((void**)&x16, g_x16);
    cudaGetSymbolAddress((void**)&WqT, g_WqT);
    cudaGetSymbolAddress((void**)&WkT, g_WkT);
    cudaGetSymbolAddress((void**)&WvT, g_WvT);
    cudaGetSymbolAddress((void**)&lwT, g_lwT);
    cudaGetSymbolAddress((void**)&w1T, g_w1T);
    cudaGetSymbolAddress((void**)&w2T, g_w2T);
    cudaGetSymbolAddress((void**)&Q16, g_Q16);
    cudaGetSymbolAddress((void**)&K16, g_K16);
    cudaGetSymbolAddress((void**)&V16, g_V16);
    cudaGetSymbolAddress((void**)&Vt,  g_Vt);
    cudaGetSymbolAddress((void**)&S,   g_S);
    cudaGetSymbolAddress((void**)&S16, g_S16);
    cudaGetSymbolAddress((void**)&A16, g_A16);
    cudaGetSymbolAddress((void**)&Mha, g_Mha);
    cudaGetSymbolAddress((void**)&H,   g_H);
    cudaGetSymbolAddress((void**)&H16, g_H16);
    cudaGetSymbolAddress((void**)&F1,  g_F1);
    cudaGetSymbolAddress((void**)&F2,  g_F2);

    dim3 blk(256);
    dim3 tblk(32, 8);

    // ---- prep: cvt + transposed fp16 weights ----
    cvt16<<<(TOK*512 + 255)/256, 256>>>(x, x16, TOK*512);
    transpose_cvt<<<dim3(2, 16, 8), tblk>>>(qw, WqT, 512, 64, 512*64, 64*512);
    transpose_cvt<<<dim3(2, 16, 8), tblk>>>(kw, WkT, 512, 64, 512*64, 64*512);
    transpose_cvt<<<dim3(16, 16, 8), tblk>>>(vw, WvT, 512, 512, 512*512, 512*512);
    transpose_cvt<<<dim3(16, 128, 1), tblk>>>(lw, lwT, 4096, 512, 0, 0);
    transpose_cvt<<<dim3(64, 16, 1), tblk>>>(w1, w1T, 512, 2048, 0, 0);
    transpose_cvt<<<dim3(16, 64, 1), tblk>>>(w2, w2T, 2048, 512, 0, 0);

    // ---- Q,K,V projections ----
    gemm16<<<dim3(4, 64, 1), blk>>>(x16, WqT, nullptr, Q16, 8192, 512, 512,
                                    512, 512, 512, 0,0,0,0,0,0, 1, nullptr, 0);
    gemm16<<<dim3(4, 64, 1), blk>>>(x16, WkT, nullptr, K16, 8192, 512, 512,
                                    512, 512, 512, 0,0,0,0,0,0, 1, nullptr, 0);
    gemm16<<<dim3(32, 64, 1), blk>>>(x16, WvT, nullptr, V16, 8192, 4096, 512,
                                     512, 512, 4096, 0,0,0,0,0,0, 1, nullptr, 0);
    transpose_v<<<dim3(16, 32, 64), tblk>>>(V16, Vt);

    // ---- scores = Q K^T (per z=(b,h), K=64) -> fp32 S ----
    gemm16<<<dim3(8, 8, 64), blk>>>(Q16, K16, S, nullptr, 1024, 1024, 64,
                                    512, 512, 1024,
                                    1024LL*512, 64, 1024LL*512, 64,
                                    8LL*1024*1024, 1024LL*1024, 8, nullptr, 0);

    softmax_1024<<<64 * 1024, 256>>>(S, S16, 1.0f / sqrtf(512.0f));

    // ---- attn = P @ V^T (B = Vt[z][e][t]) -> A16 concat-head ----
    gemm16<<<dim3(4, 8, 64), blk>>>(S16, Vt, nullptr, A16, 1024, 512, 1024,
                                    1024, 1024, 4096,
                                    8LL*1024*1024, 1024LL*1024,
                                    8LL*512*1024, 512LL*1024,
                                    1024LL*4096, 512, 8, nullptr, 0);

    // ---- mha = A16 @ lw -> fp32 ----
    gemm16<<<dim3(4, 64, 1), blk>>>(A16, lwT, Mha, nullptr, 8192, 512, 4096,
                                    4096, 4096, 512, 0,0,0,0,0,0, 1, nullptr, 0);

    add_ln<<<8192, 128>>>(x, Mha, gamma1, beta1, H, H16);

    // ---- FFN ----
    gemm16<<<dim3(16, 64, 1), blk>>>(H16, w1T, nullptr, F1, 8192, 2048, 512,
                                     512, 512, 2048, 0,0,0,0,0,0, 1, b1, 1);
    gemm16<<<dim3(4, 64, 1), blk>>>(F1, w2T, F2, nullptr, 8192, 512, 2048,
                                    2048, 2048, 512, 0,0,0,0,0,0, 1, b2, 0);

    add_ln<<<8192, 128>>>(H, F2, gamma2, beta2, out, nullptr);
}